// round 16
// baseline (speedup 1.0000x reference)
#include <cuda_runtime.h>
#include <cuda_bf16.h>
#include <cuda_fp16.h>
#include <stdint.h>
#include <math.h>

#define DD   1024
#define NH   16
#define HDIM 64
#define BB   2
#define LL   2048
#define MTOK (BB*LL)   // 4096

#define AK64 72    // [row][k64] 16-bit smem stride (64 + 8)
#define BKS 136    // combine [k][n128] stride (128 + 8)
#define BNS 264    // qkv [k][n256] stride (256 + 8)

#define LOG2E  1.4426950408889634f
#define INV32  0.03125f

// ---------------- scratch (device globals; no allocations allowed) ----------
__device__ __half g_Wch[3][DD*DD], g_Wcl[3][DD*DD];  // 32*(W^T@R) fp16 split [k][n]
__device__ __half g_Xf[MTOK*DD];                     // X fp16 [m][k]
__device__ __half g_Woh[DD*DD],  g_Wol[DD*DD];       // 32*Wo fp16 split [n][k]
__device__ __half g_Of[MTOK*DD];                     // attn out fp16 (B,L,D)
// fp16 attention operands, mma-fragment-native layouts:
// Q,K: [b][h][l][perm(d)]; Q pre-scaled by ent/8*log2e. V: [b][h][l>>6][d][perm(l&63)]
__device__ __half g_Qf[BB*NH*LL*HDIM];
__device__ __half g_Kf[BB*NH*LL*HDIM];
__device__ __half g_Vt[BB*NH*LL*HDIM];

// ---------------- helpers ----------------------------------------------------
__device__ __forceinline__ float ex2(float x) {
    float y;
    asm("ex2.approx.f32 %0, %1;" : "=f"(y) : "f"(x));
    return y;
}
__device__ __forceinline__ uint32_t ex2h2(float a, float b) {
    __half2 h = __floats2half2_rn(a, b);
    uint32_t r;
    asm("ex2.approx.f16x2 %0, %1;" : "=r"(r) : "r"(*(uint32_t*)&h));
    return r;
}

__device__ __forceinline__ void mma16(float* d, const uint32_t* a, const uint32_t* b) {
    asm volatile(
        "mma.sync.aligned.m16n8k16.row.col.f32.bf16.bf16.f32 "
        "{%0,%1,%2,%3}, {%4,%5,%6,%7}, {%8,%9}, {%0,%1,%2,%3};"
        : "+f"(d[0]), "+f"(d[1]), "+f"(d[2]), "+f"(d[3])
        : "r"(a[0]), "r"(a[1]), "r"(a[2]), "r"(a[3]), "r"(b[0]), "r"(b[1]));
}
__device__ __forceinline__ void mma16h(float* d, const uint32_t* a, const uint32_t* b) {
    asm volatile(
        "mma.sync.aligned.m16n8k16.row.col.f32.f16.f16.f32 "
        "{%0,%1,%2,%3}, {%4,%5,%6,%7}, {%8,%9}, {%0,%1,%2,%3};"
        : "+f"(d[0]), "+f"(d[1]), "+f"(d[2]), "+f"(d[3])
        : "r"(a[0]), "r"(a[1]), "r"(a[2]), "r"(a[3]), "r"(b[0]), "r"(b[1]));
}

__device__ __forceinline__ void ldsm4(uint32_t* r, const void* p) {
    uint32_t a = (uint32_t)__cvta_generic_to_shared(p);
    asm volatile("ldmatrix.sync.aligned.m8n8.x4.shared.b16 {%0,%1,%2,%3}, [%4];"
        : "=r"(r[0]), "=r"(r[1]), "=r"(r[2]), "=r"(r[3]) : "r"(a));
}
__device__ __forceinline__ void ldsm4t(uint32_t* r, const void* p) {
    uint32_t a = (uint32_t)__cvta_generic_to_shared(p);
    asm volatile("ldmatrix.sync.aligned.m8n8.x4.trans.shared.b16 {%0,%1,%2,%3}, [%4];"
        : "=r"(r[0]), "=r"(r[1]), "=r"(r[2]), "=r"(r[3]) : "r"(a));
}

__device__ __forceinline__ void cpa16(void* smem, const void* gmem) {
    uint32_t s = (uint32_t)__cvta_generic_to_shared(smem);
    asm volatile("cp.async.cg.shared.global [%0], [%1], 16;" :: "r"(s), "l"(gmem) : "memory");
}
#define CP_COMMIT() asm volatile("cp.async.commit_group;" ::: "memory")
#define CP_WAIT0()  asm volatile("cp.async.wait_group 0;" ::: "memory")
#define CP_WAIT1()  asm volatile("cp.async.wait_group 1;" ::: "memory")

// split 4 fp32 -> bf16 hi/lo (combine's smem staging)
__device__ __forceinline__ void sst4(__nv_bfloat16* hp, __nv_bfloat16* lp, float4 v) {
    __nv_bfloat16 hx = __float2bfloat16_rn(v.x), hy = __float2bfloat16_rn(v.y);
    __nv_bfloat16 hz = __float2bfloat16_rn(v.z), hw = __float2bfloat16_rn(v.w);
    __nv_bfloat162* H = (__nv_bfloat162*)hp;
    H[0] = __halves2bfloat162(hx, hy);
    H[1] = __halves2bfloat162(hz, hw);
    __nv_bfloat162* L = (__nv_bfloat162*)lp;
    L[0] = __halves2bfloat162(__float2bfloat16_rn(v.x - __bfloat162float(hx)),
                              __float2bfloat16_rn(v.y - __bfloat162float(hy)));
    L[1] = __halves2bfloat162(__float2bfloat16_rn(v.z - __bfloat162float(hz)),
                              __float2bfloat16_rn(v.w - __bfloat162float(hw)));
}

// split scalar fp32 -> fp16 hi/lo
__device__ __forceinline__ void sp1h(__half* ph, __half* pl, float v) {
    __half h = __float2half_rn(v);
    *ph = h;
    *pl = __float2half_rn(v - __half2float(h));
}

// ============================================================================
// Kernel 1: Wc[z] = W[z]^T @ R  (TN), bf16x3 (accurate); stores 32*Wc as fp16
// hi/lo [k][n]. FUSED PROLOGUE: converts X -> fp16 and Wo*32 -> fp16 hi/lo.
// ============================================================================
__global__ __launch_bounds__(256) void combine_b3(
    const float* __restrict__ Wq, const float* __restrict__ Wk,
    const float* __restrict__ Wv, const float* __restrict__ R,
    const float* __restrict__ X, const float* __restrict__ Wo)
{
    const int tid = threadIdx.x;

    // ---- fused convert (X, Wo) ----
    {
        int cid = blockIdx.x + (blockIdx.y << 3) + (blockIdx.z << 6); // 0..191
        int i0 = cid * 256 + tid;
        int st = 192 * 256;
        for (int i = i0; i < MTOK * DD / 4; i += st) {
            float4 v = ((const float4*)X)[i];
            __half2* H = (__half2*)&g_Xf[i * 4];
            H[0] = __floats2half2_rn(v.x, v.y);
            H[1] = __floats2half2_rn(v.z, v.w);
        }
        for (int i = i0; i < DD * DD / 4; i += st) {
            float4 v = ((const float4*)Wo)[i];
            sp1h(&g_Woh[i * 4 + 0], &g_Wol[i * 4 + 0], v.x * 32.0f);
            sp1h(&g_Woh[i * 4 + 1], &g_Wol[i * 4 + 1], v.y * 32.0f);
            sp1h(&g_Woh[i * 4 + 2], &g_Wol[i * 4 + 2], v.z * 32.0f);
            sp1h(&g_Woh[i * 4 + 3], &g_Wol[i * 4 + 3], v.w * 32.0f);
        }
    }

    const int z = blockIdx.z;
    const float* W = (z == 0) ? Wq : ((z == 1) ? Wk : Wv);

    __shared__ __align__(16) __nv_bfloat16 Ath[32][BKS], Atl[32][BKS];
    __shared__ __align__(16) __nv_bfloat16 Bth[32][BKS], Btl[32][BKS];

    const int lane = tid & 31, g = lane >> 2, t = lane & 3;
    const int warp = tid >> 5, wm = warp >> 2, wn = warp & 3;
    const int i0 = blockIdx.y * 128, j0 = blockIdx.x * 128;
    const int kr = tid >> 5, cc = (tid & 31) * 4;

    float acc[4][4][4] = {};
    float4 pa[4], pb[4];
    #pragma unroll
    for (int r = 0; r < 4; r++) {
        pa[r] = *(const float4*)&W[(size_t)(kr + r * 8) * DD + i0 + cc];
        pb[r] = *(const float4*)&R[(size_t)(kr + r * 8) * DD + j0 + cc];
    }

    for (int kt = 0; kt < DD; kt += 32) {
        #pragma unroll
        for (int r = 0; r < 4; r++) {
            sst4(&Ath[kr + r * 8][cc], &Atl[kr + r * 8][cc], pa[r]);
            sst4(&Bth[kr + r * 8][cc], &Btl[kr + r * 8][cc], pb[r]);
        }
        __syncthreads();
        if (kt + 32 < DD) {
            #pragma unroll
            for (int r = 0; r < 4; r++) {
                pa[r] = *(const float4*)&W[(size_t)(kt + 32 + kr + r * 8) * DD + i0 + cc];
                pb[r] = *(const float4*)&R[(size_t)(kt + 32 + kr + r * 8) * DD + j0 + cc];
            }
        }
        #pragma unroll
        for (int ks = 0; ks < 2; ks++) {
            const int kk0 = ks * 16;
            uint32_t ah[4][4], al[4][4], bh[2][4], bl[2][4];
            const int arow = kk0 + (lane >> 4) * 8 + (lane & 7);
            const int acol = wm * 64 + ((lane >> 3) & 1) * 8;
            #pragma unroll
            for (int mi = 0; mi < 4; mi++) {
                ldsm4t(ah[mi], &Ath[arow][acol + mi * 16]);
                ldsm4t(al[mi], &Atl[arow][acol + mi * 16]);
            }
            const int brow = kk0 + (lane & 7) + ((lane >> 3) & 1) * 8;
            const int bcol = wn * 32 + (lane >> 4) * 8;
            #pragma unroll
            for (int nj = 0; nj < 2; nj++) {
                ldsm4t(bh[nj], &Bth[brow][bcol + nj * 16]);
                ldsm4t(bl[nj], &Btl[brow][bcol + nj * 16]);
            }
            #pragma unroll
            for (int mi = 0; mi < 4; mi++)
                #pragma unroll
                for (int nj = 0; nj < 2; nj++)
                    #pragma unroll
                    for (int h2 = 0; h2 < 2; h2++) {
                        float* c = acc[mi][nj * 2 + h2];
                        mma16(c, ah[mi], &bh[nj][h2 * 2]);
                        mma16(c, ah[mi], &bl[nj][h2 * 2]);
                        mma16(c, al[mi], &bh[nj][h2 * 2]);
                    }
        }
        __syncthreads();
    }

    __half* Ch = g_Wch[z];
    __half* Cl = g_Wcl[z];
    #pragma unroll
    for (int mi = 0; mi < 4; mi++) {
        int row0 = i0 + wm * 64 + mi * 16 + g;      // k index of Wc
        #pragma unroll
        for (int ni = 0; ni < 4; ni++) {
            int col = j0 + wn * 32 + ni * 8 + 2 * t; // n index of Wc
            sp1h(&Ch[(size_t)row0 * DD + col],     &Cl[(size_t)row0 * DD + col],
                 acc[mi][ni][0] * 32.0f);
            sp1h(&Ch[(size_t)row0 * DD + col + 1], &Cl[(size_t)row0 * DD + col + 1],
                 acc[mi][ni][1] * 32.0f);
            sp1h(&Ch[(size_t)(row0 + 8) * DD + col],     &Cl[(size_t)(row0 + 8) * DD + col],
                 acc[mi][ni][2] * 32.0f);
            sp1h(&Ch[(size_t)(row0 + 8) * DD + col + 1], &Cl[(size_t)(row0 + 8) * DD + col + 1],
                 acc[mi][ni][3] * 32.0f);
        }
    }
}

// ============================================================================
// Kernel 2: P = X @ (32*Wc[z]) (NN), fp16x2, CTA tile 128x256, warp tile
// 64x64 (2x4 warp grid), K64 double-buffered cp.async, 1 CTA/SM.
// buffer: A 128x72 + Bh 64x264 + Bl 64x264 = 43008 halfs = 86 KB
// ============================================================================
#define QA_BUF 9216
#define QB_BUF 16896
#define QBUF   (QA_BUF + 2 * QB_BUF)
#define QKV_SMEM (2 * QBUF * 2)

__global__ __launch_bounds__(256, 1) void qkv_f2(const float* __restrict__ ent)
{
    extern __shared__ __half qsm[];
    const int z = blockIdx.z;
    const __half* Wh = g_Wch[z];
    const __half* Wl = g_Wcl[z];

    const int tid = threadIdx.x, lane = tid & 31, g = lane >> 2, t = lane & 3;
    const int warp = tid >> 5, wm = warp >> 2, wn = warp & 3;   // 2 x 4
    const int m0 = blockIdx.y * 128, j0 = blockIdx.x * 256;
    const int b = m0 >> 11;

    auto fill = [&](int bi, int kt) {
        __half* A  = qsm + bi * QBUF;
        __half* Bh = A + QA_BUF;
        __half* Bl = Bh + QB_BUF;
        #pragma unroll
        for (int i = 0; i < 4; i++) {
            int idx = tid + i * 256;
            int row = idx >> 3, ch = idx & 7;       // A: 128 rows x 64 cols
            cpa16(&A[row * AK64 + ch * 8], &g_Xf[(size_t)(m0 + row) * DD + kt + ch * 8]);
        }
        #pragma unroll
        for (int i = 0; i < 8; i++) {
            int idx = tid + i * 256;
            int row = idx >> 5, ch = idx & 31;      // B: 64 k-rows x 256 cols
            size_t src = (size_t)(kt + row) * DD + j0 + ch * 8;
            cpa16(&Bh[row * BNS + ch * 8], &Wh[src]);
            cpa16(&Bl[row * BNS + ch * 8], &Wl[src]);
        }
    };

    float acc[4][8][4] = {};

    fill(0, 0);  CP_COMMIT();
    fill(1, 64); CP_COMMIT();

    const int NT = DD / 64;   // 16
    for (int it = 0; it < NT; ++it) {
        if (it == NT - 1) { CP_WAIT0(); } else { CP_WAIT1(); }
        __syncthreads();
        const __half* A  = qsm + (it & 1) * QBUF;
        const __half* Bh = A + QA_BUF;
        const __half* Bl = Bh + QB_BUF;
        #pragma unroll
        for (int ks = 0; ks < 4; ks++) {
            const int kk0 = ks * 16;
            uint32_t ah[4][4], bh[4][4], bl[4][4];
            const int arow = wm * 64 + (lane & 15);
            const int ak   = kk0 + (lane >> 4) * 8;
            #pragma unroll
            for (int mi = 0; mi < 4; mi++)
                ldsm4(ah[mi], &A[(arow + mi * 16) * AK64 + ak]);
            const int brow = kk0 + (lane & 7) + ((lane >> 3) & 1) * 8;
            const int bcol = wn * 64 + (lane >> 4) * 8;
            #pragma unroll
            for (int nj = 0; nj < 4; nj++) {
                ldsm4t(bh[nj], &Bh[brow * BNS + bcol + nj * 16]);
                ldsm4t(bl[nj], &Bl[brow * BNS + bcol + nj * 16]);
            }
            #pragma unroll
            for (int mi = 0; mi < 4; mi++)
                #pragma unroll
                for (int nj = 0; nj < 4; nj++)
                    #pragma unroll
                    for (int h2 = 0; h2 < 2; h2++) {
                        float* c = acc[mi][nj * 2 + h2];
                        mma16h(c, ah[mi], &bh[nj][h2 * 2]);
                        mma16h(c, ah[mi], &bl[nj][h2 * 2]);
                    }
        }
        __syncthreads();
        if (it + 2 < NT) { fill(it & 1, (it + 2) * 64); CP_COMMIT(); }
    }

    if (z < 2) {
        __half* OutH = (z == 0) ? g_Qf : g_Kf;
        #pragma unroll
        for (int ni = 0; ni < 8; ni++) {
            int n = j0 + wn * 64 + ni * 8 + 2 * t;    // even
            int h = n >> 6, d = n & 63;
            int pos = (d & 0x30) | ((d & 6) << 1) | ((d & 8) >> 2);
            float s = (z == 0) ? (ent[h] * 0.125f * LOG2E * INV32) : INV32;
            #pragma unroll
            for (int mi = 0; mi < 4; mi++) {
                int m = m0 + wm * 64 + mi * 16 + g;
                int l = m & (LL - 1);
                size_t base = ((size_t)(b * NH + h) * LL + l) * HDIM + pos;
                *(__half2*)&OutH[base] =
                    __floats2half2_rn(acc[mi][ni][0] * s, acc[mi][ni][1] * s);
                *(__half2*)&OutH[base + 8 * HDIM] =
                    __floats2half2_rn(acc[mi][ni][2] * s, acc[mi][ni][3] * s);
            }
        }
    } else {
        #pragma unroll
        for (int ni = 0; ni < 8; ni++) {
            int n = j0 + wn * 64 + ni * 8 + 2 * t;
            int h = n >> 6, d = n & 63;               // d even
            #pragma unroll
            for (int mi = 0; mi < 4; mi++) {
                int m = m0 + wm * 64 + mi * 16 + g;
                int l = m & (LL - 1);
                int l6 = l & 63;
                int pos = (l6 & 0x30) | ((l6 & 6) << 1) | ((l6 & 8) >> 2) | (l6 & 1);
                size_t base = (size_t)(b * NH + h) * LL * HDIM
                            + (size_t)(l >> 6) * 4096 + (size_t)d * 64;
                g_Vt[base + pos]          = __float2half_rn(acc[mi][ni][0] * INV32);
                g_Vt[base + 64 + pos]     = __float2half_rn(acc[mi][ni][1] * INV32);
                g_Vt[base + pos + 2]      = __float2half_rn(acc[mi][ni][2] * INV32);
                g_Vt[base + 64 + pos + 2] = __float2half_rn(acc[mi][ni][3] * INV32);
            }
        }
    }
}

// ============================================================================
// Kernel 3: flash attention v7 — fp16 mma; f16x2 ex2 softmax; l carried as a
// 65th V dim (ones-row mma). Unchanged from R15.
// smem: K 2x64x80 + V 2x72x80 halfs = 43520 B.
// ============================================================================
#define FQS   80
#define KBUF  5120
#define VBUF  5760
#define VBASE 10240
#define FL7_SMEM ((2 * KBUF + 2 * VBUF) * 2)

__global__ __launch_bounds__(256, 1) void flash7()
{
    extern __shared__ __half hsm[];
    const int tid = threadIdx.x, lane = tid & 31, g = lane >> 2, t = lane & 3;
    const int warp = tid >> 5;

    const int bh = blockIdx.y;
    const size_t head = (size_t)bh * LL * HDIM;
    const int q0 = blockIdx.x * 256 + warp * 32;

    uint32_t qa[2][4][4];
    #pragma unroll
    for (int mt = 0; mt < 2; mt++)
        #pragma unroll
        for (int kc = 0; kc < 4; kc++) {
            const __half* qp = &g_Qf[head + (size_t)(q0 + mt * 16 + g) * HDIM + kc * 16 + t * 4];
            uint2 u0 = *(const uint2*)qp;
            uint2 u1 = *(const uint2*)(qp + 8 * HDIM);
            qa[mt][kc][0] = u0.x; qa[mt][kc][1] = u1.x;
            qa[mt][kc][2] = u0.y; qa[mt][kc][3] = u1.y;
        }

    const int frow = tid >> 2;
    const int fch  = (tid & 3) * 2;

    float o[2][8][4] = {};
    float oe[2][4] = {};   // l rides here (ones-row mma output)
    float mv[2][2] = {{-1e30f, -1e30f}, {-1e30f, -1e30f}};

    for (int i = tid; i < 2 * 8 * FQS; i += 256) {
        int bi = i / (8 * FQS), rc = i % (8 * FQS);
        int r = rc / FQS, c = rc % FQS;
        hsm[VBASE + bi * VBUF + (64 + r) * FQS + c] =
            __float2half(r == 0 ? 1.0f : 0.0f);
    }

    {
        const __half* Ks = g_Kf + head;
        const __half* Vs = g_Vt + head;
        #pragma unroll
        for (int i = 0; i < 2; i++) {
            int ch = fch + i;
            cpa16(&hsm[frow * FQS + ch * 8],         &Ks[frow * 64 + ch * 8]);
            cpa16(&hsm[VBASE + frow * FQS + ch * 8], &Vs[frow * 64 + ch * 8]);
        }
    }
    CP_COMMIT();

    for (int it = 0; it < LL / 64; ++it) {
        CP_WAIT0();
        __syncthreads();
        if (it + 1 < LL / 64) {
            const __half* Ks = g_Kf + head + (size_t)(it + 1) * 4096;
            const __half* Vs = g_Vt + head + (size_t)(it + 1) * 4096;
            __half* Kd = hsm + ((it + 1) & 1) * KBUF;
            __half* Vd = hsm + VBASE + ((it + 1) & 1) * VBUF;
            #pragma unroll
            for (int i = 0; i < 2; i++) {
                int ch = fch + i;
                cpa16(&Kd[frow * FQS + ch * 8], &Ks[frow * 64 + ch * 8]);
                cpa16(&Vd[frow * FQS + ch * 8], &Vs[frow * 64 + ch * 8]);
            }
            CP_COMMIT();
        }
        const __half* Ksm = hsm + (it & 1) * KBUF;
        const __half* Vsm = hsm + VBASE + (it & 1) * VBUF;

        float s[2][8][4] = {};
        #pragma unroll
        for (int kc = 0; kc < 4; kc++) {
            #pragma unroll
            for (int nt = 0; nt < 8; nt++) {
                uint2 bv = *(const uint2*)&Ksm[(nt * 8 + g) * FQS + kc * 16 + t * 4];
                uint32_t bf[2] = { bv.x, bv.y };
                mma16h(s[0][nt], qa[0][kc], bf);
                mma16h(s[1][nt], qa[1][kc], bf);
            }
        }

        uint32_t pr[2][8][2];
        #pragma unroll
        for (int mt = 0; mt < 2; mt++) {
            float rmax0 = -1e30f, rmax1 = -1e30f;
            #pragma unroll
            for (int nt = 0; nt < 8; nt++) {
                rmax0 = fmaxf(rmax0, fmaxf(s[mt][nt][0], s[mt][nt][1]));
                rmax1 = fmaxf(rmax1, fmaxf(s[mt][nt][2], s[mt][nt][3]));
            }
            rmax0 = fmaxf(rmax0, __shfl_xor_sync(0xffffffffu, rmax0, 1));
            rmax0 = fmaxf(rmax0, __shfl_xor_sync(0xffffffffu, rmax0, 2));
            rmax1 = fmaxf(rmax1, __shfl_xor_sync(0xffffffffu, rmax1, 1));
            rmax1 = fmaxf(rmax1, __shfl_xor_sync(0xffffffffu, rmax1, 2));

            float nm0 = fmaxf(mv[mt][0], rmax0), nm1 = fmaxf(mv[mt][1], rmax1);
            float c0 = ex2(mv[mt][0] - nm0), c1 = ex2(mv[mt][1] - nm1);
            mv[mt][0] = nm0; mv[mt][1] = nm1;

            #pragma unroll
            for (int nt = 0; nt < 8; nt++) {
                o[mt][nt][0] *= c0; o[mt][nt][1] *= c0;
                o[mt][nt][2] *= c1; o[mt][nt][3] *= c1;
            }
            oe[mt][0] *= c0; oe[mt][1] *= c0;
            oe[mt][2] *= c1; oe[mt][3] *= c1;

            #pragma unroll
            for (int nt = 0; nt < 8; nt++) {
                pr[mt][nt][0] = ex2h2(s[mt][nt][0] - nm0, s[mt][nt][1] - nm0);
                pr[mt][nt][1] = ex2h2(s[mt][nt][2] - nm1, s[mt][nt][3] - nm1);
            }
        }

        #pragma unroll
        for (int kc = 0; kc < 4; kc++) {
            uint32_t pa[2][4];
            #pragma unroll
            for (int mt = 0; mt < 2; mt++) {
                pa[mt][0] = pr[mt][2 * kc][0];
                pa[mt][1] = pr[mt][2 * kc][1];
                pa[mt][2] = pr[mt][2 * kc + 1][0];
                pa[mt][3] = pr[mt][2 * kc + 1][1];
            }
            #pragma unroll
            for (int nt = 0; nt < 8; nt++) {
                uint2 bv = *(const uint2*)&Vsm[(nt * 8 + g) * FQS + kc * 16 + t * 4];
                uint32_t bf[2] = { bv.x, bv.y };
                mma16h(o[0][nt], pa[0], bf);
                mma16h(o[1][nt], pa[1], bf);
            }
            uint2 ev = *(const uint2*)&Vsm[(64 + g) * FQS + kc * 16 + t * 4];
            uint32_t ef[2] = { ev.x, ev.y };
            mma16h(oe[0], pa[0], ef);
            mma16h(oe[1], pa[1], ef);
        }
    }

    const int b = bh >> 4, h = bh & 15;
    #pragma unroll
    for (int mt = 0; mt < 2; mt++) {
        float l0 = __shfl_sync(0xffffffffu, oe[mt][0], lane & 28);
        float l1 = __shfl_sync(0xffffffffu, oe[mt][2], lane & 28);
        float inv0 = 1.0f / l0, inv1 = 1.0f / l1;
        size_t ob0 = ((size_t)b * LL + q0 + mt * 16 + g) * DD + h * HDIM;
        size_t ob1 = ((size_t)b * LL + q0 + mt * 16 + 8 + g) * DD + h * HDIM;
        #pragma unroll
        for (int nt = 0; nt < 8; nt++) {
            int col = nt * 8 + 2 * t;
            *(__half2*)&g_Of[ob0 + col] =
                __floats2half2_rn(o[mt][nt][0] * inv0, o[mt][nt][1] * inv0);
            *(__half2*)&g_Of[ob1 + col] =
                __floats2half2_rn(o[mt][nt][2] * inv1, o[mt][nt][3] * inv1);
        }
    }
}

// ============================================================================
// Kernel 4: Y = O @ (32*Wo)^T / 32 (NT), fp16x2, CTA tile 128x256, warp tile
// 64x64, K64 double-buffered, 1 CTA/SM. grid (4,32)=128 CTAs -> single wave.
// buffer: A 128x72 + Bh 256x72 + Bl 256x72 = 46080 halfs = 92 KB
// ============================================================================
#define OA_BUF 9216
#define OB_BUF 18432
#define OBUF   (OA_BUF + 2 * OB_BUF)
#define OUT_SMEM (2 * OBUF * 2)

__global__ __launch_bounds__(256, 1) void out_f2(float* __restrict__ Y)
{
    extern __shared__ __half osm[];
    const int tid = threadIdx.x, lane = tid & 31, g = lane >> 2, t = lane & 3;
    const int warp = tid >> 5, wm = warp >> 2, wn = warp & 3;   // 2 x 4
    const int m0 = blockIdx.y * 128, j0 = blockIdx.x * 256;

    auto fill = [&](int bi, int kt) {
        __half* A  = osm + bi * OBUF;
        __half* Bh = A + OA_BUF;
        __half* Bl = Bh + OB_BUF;
        #pragma unroll
        for (int i = 0; i < 4; i++) {
            int idx = tid + i * 256;
            int row = idx >> 3, ch = idx & 7;   // A: 128 rows x 64 cols
            cpa16(&A[row * AK64 + ch * 8], &g_Of[(size_t)(m0 + row) * DD + kt + ch * 8]);
        }
        #pragma unroll
        for (int i = 0; i < 8; i++) {
            int idx = tid + i * 256;
            int row = idx >> 3, ch = idx & 7;   // B: 256 n-rows x 64 cols
            size_t src = (size_t)(j0 + row) * DD + kt + ch * 8;
            cpa16(&Bh[row * AK64 + ch * 8], &g_Woh[src]);
            cpa16(&Bl[row * AK64 + ch * 8], &g_Wol[src]);
        }
    };

    float acc[4][8][4] = {};

    fill(0, 0);  CP_COMMIT();
    fill(1, 64); CP_COMMIT();

    const int NT = DD / 64;   // 16
    for (int it = 0; it < NT; ++it) {
        if (it == NT - 1) { CP_WAIT0(); } else { CP_WAIT1(); }
        __syncthreads();
        const __half* A  = osm + (it & 1) * OBUF;
        const __half* Bh = A + OA_BUF;
        const __half* Bl = Bh + OB_BUF;
        #pragma unroll
        for (int ks = 0; ks < 4; ks++) {
            const int kk0 = ks * 16;
            uint32_t ah[4][4], bh[4][4], bl[4][4];
            const int arow = wm * 64 + (lane & 15);
            const int ak   = kk0 + (lane >> 4) * 8;
            #pragma unroll
            for (int mi = 0; mi < 4; mi++)
                ldsm4(ah[mi], &A[(arow + mi * 16) * AK64 + ak]);
            const int brow = wn * 64 + (lane & 7) + ((lane >> 4) & 1) * 8;
            const int bk   = kk0 + ((lane >> 3) & 1) * 8;
            #pragma unroll
            for (int nj = 0; nj < 4; nj++) {
                ldsm4(bh[nj], &Bh[(brow + nj * 16) * AK64 + bk]);
                ldsm4(bl[nj], &Bl[(brow + nj * 16) * AK64 + bk]);
            }
            #pragma unroll
            for (int mi = 0; mi < 4; mi++)
                #pragma unroll
                for (int nj = 0; nj < 4; nj++)
                    #pragma unroll
                    for (int h2 = 0; h2 < 2; h2++) {
                        float* c = acc[mi][nj * 2 + h2];
                        mma16h(c, ah[mi], &bh[nj][h2 * 2]);
                        mma16h(c, ah[mi], &bl[nj][h2 * 2]);
                    }
        }
        __syncthreads();
        if (it + 2 < NT) { fill(it & 1, (it + 2) * 64); CP_COMMIT(); }
    }

    #pragma unroll
    for (int mi = 0; mi < 4; mi++) {
        int row0 = m0 + wm * 64 + mi * 16 + g;
        #pragma unroll
        for (int ni = 0; ni < 8; ni++) {
            int col = j0 + wn * 64 + ni * 8 + 2 * t;
            *(float2*)&Y[(size_t)row0 * DD + col] =
                make_float2(acc[mi][ni][0] * INV32, acc[mi][ni][1] * INV32);
            *(float2*)&Y[(size_t)(row0 + 8) * DD + col] =
                make_float2(acc[mi][ni][2] * INV32, acc[mi][ni][3] * INV32);
        }
    }
}

// ============================================================================
// launch
// Inputs: 0=inputs 1=rotation 2=entangle 3=Wq 4=Wk 5=Wv 6=Wo; out (B,L,D) fp32
// ============================================================================
extern "C" void kernel_launch(void* const* d_in, const int* in_sizes, int n_in,
                              void* d_out, int out_size)
{
    const float* X   = (const float*)d_in[0];
    const float* R   = (const float*)d_in[1];
    const float* ent = (const float*)d_in[2];
    const float* Wq  = (const float*)d_in[3];
    const float* Wk  = (const float*)d_in[4];
    const float* Wv  = (const float*)d_in[5];
    const float* Wo  = (const float*)d_in[6];
    float* Y = (float*)d_out;

    cudaFuncSetAttribute(flash7, cudaFuncAttributeMaxDynamicSharedMemorySize, FL7_SMEM);
    cudaFuncSetAttribute(qkv_f2, cudaFuncAttributeMaxDynamicSharedMemorySize, QKV_SMEM);
    cudaFuncSetAttribute(out_f2, cudaFuncAttributeMaxDynamicSharedMemorySize, OUT_SMEM);

    combine_b3<<<dim3(8, 8, 3), 256>>>(Wq, Wk, Wv, R, X, Wo);
    qkv_f2<<<dim3(DD / 256, MTOK / 128, 3), 256, QKV_SMEM>>>(ent);
    flash7<<<dim3(LL / 256, BB * NH), 256, FL7_SMEM>>>();
    out_f2<<<dim3(DD / 256, MTOK / 128), 256, OUT_SMEM>>>(Y);
}

// round 17
// speedup vs baseline: 1.1326x; 1.1326x over previous
#include <cuda_runtime.h>
#include <cuda_fp16.h>
#include <stdint.h>
#include <math.h>

#define DD   1024
#define NH   16
#define HDIM 64
#define BB   2
#define LL   2048
#define MTOK (BB*LL)   // 4096

#define AK64 72    // [row][k64] 16-bit smem stride (64 + 8)
#define BKS 136    // [k][n128] 16-bit smem stride (128 + 8)

#define LOG2E  1.4426950408889634f
#define INV32  0.03125f

// ---------------- scratch (device globals; no allocations allowed) ----------
__device__ __half g_Wch[3][DD*DD], g_Wcl[3][DD*DD];  // 32*(W^T@R) fp16 split [k][n]
__device__ __half g_Xf[MTOK*DD];                     // X fp16 [m][k]
__device__ __half g_Woh[DD*DD],  g_Wol[DD*DD];       // 32*Wo fp16 split [n][k]
__device__ __half g_Of[MTOK*DD];                     // attn out fp16 (B,L,D)
// fp16 attention operands, mma-fragment-native layouts:
// Q,K: [b][h][l][perm(d)]; Q pre-scaled by ent/8*log2e. V: [b][h][l>>6][d][perm(l&63)]
__device__ __half g_Qf[BB*NH*LL*HDIM];
__device__ __half g_Kf[BB*NH*LL*HDIM];
__device__ __half g_Vt[BB*NH*LL*HDIM];

// ---------------- helpers ----------------------------------------------------
__device__ __forceinline__ float ex2(float x) {
    float y;
    asm("ex2.approx.f32 %0, %1;" : "=f"(y) : "f"(x));
    return y;
}
__device__ __forceinline__ uint32_t ex2h2(float a, float b) {
    __half2 h = __floats2half2_rn(a, b);
    uint32_t r;
    asm("ex2.approx.f16x2 %0, %1;" : "=r"(r) : "r"(*(uint32_t*)&h));
    return r;
}

__device__ __forceinline__ void mma16h(float* d, const uint32_t* a, const uint32_t* b) {
    asm volatile(
        "mma.sync.aligned.m16n8k16.row.col.f32.f16.f16.f32 "
        "{%0,%1,%2,%3}, {%4,%5,%6,%7}, {%8,%9}, {%0,%1,%2,%3};"
        : "+f"(d[0]), "+f"(d[1]), "+f"(d[2]), "+f"(d[3])
        : "r"(a[0]), "r"(a[1]), "r"(a[2]), "r"(a[3]), "r"(b[0]), "r"(b[1]));
}

__device__ __forceinline__ void ldsm4(uint32_t* r, const void* p) {
    uint32_t a = (uint32_t)__cvta_generic_to_shared(p);
    asm volatile("ldmatrix.sync.aligned.m8n8.x4.shared.b16 {%0,%1,%2,%3}, [%4];"
        : "=r"(r[0]), "=r"(r[1]), "=r"(r[2]), "=r"(r[3]) : "r"(a));
}
__device__ __forceinline__ void ldsm4t(uint32_t* r, const void* p) {
    uint32_t a = (uint32_t)__cvta_generic_to_shared(p);
    asm volatile("ldmatrix.sync.aligned.m8n8.x4.trans.shared.b16 {%0,%1,%2,%3}, [%4];"
        : "=r"(r[0]), "=r"(r[1]), "=r"(r[2]), "=r"(r[3]) : "r"(a));
}

__device__ __forceinline__ void cpa16(void* smem, const void* gmem) {
    uint32_t s = (uint32_t)__cvta_generic_to_shared(smem);
    asm volatile("cp.async.cg.shared.global [%0], [%1], 16;" :: "r"(s), "l"(gmem) : "memory");
}
#define CP_COMMIT() asm volatile("cp.async.commit_group;" ::: "memory")
#define CP_WAIT0()  asm volatile("cp.async.wait_group 0;" ::: "memory")
#define CP_WAIT1()  asm volatile("cp.async.wait_group 1;" ::: "memory")

// split scalar fp32 -> fp16 hi/lo
__device__ __forceinline__ void sp1h(__half* ph, __half* pl, float v) {
    __half h = __float2half_rn(v);
    *ph = h;
    *pl = __float2half_rn(v - __half2float(h));
}
// float4 -> fp16 single (8B store)
__device__ __forceinline__ void cvt4h(__half* p, float4 v) {
    __half2* H = (__half2*)p;
    H[0] = __floats2half2_rn(v.x, v.y);
    H[1] = __floats2half2_rn(v.z, v.w);
}
// float4 -> fp16 hi/lo split (8B each)
__device__ __forceinline__ void sp4h(__half* hp, __half* lp, float4 v) {
    __half hx = __float2half_rn(v.x), hy = __float2half_rn(v.y);
    __half hz = __float2half_rn(v.z), hw = __float2half_rn(v.w);
    __half2* H = (__half2*)hp;
    H[0] = __halves2half2(hx, hy);
    H[1] = __halves2half2(hz, hw);
    __half2* L = (__half2*)lp;
    L[0] = __halves2half2(__float2half_rn(v.x - __half2float(hx)),
                          __float2half_rn(v.y - __half2float(hy)));
    L[1] = __halves2half2(__float2half_rn(v.z - __half2float(hz)),
                          __float2half_rn(v.w - __half2float(hw)));
}

// ============================================================================
// Kernel 1: Wc[z] = W[z]^T @ R  (TN), fp16x2 (W single fp16, R split hi/lo),
// inline-converted staging; stores 32*Wc as fp16 hi/lo [k][n].
// FUSED PROLOGUE: converts X -> fp16 and Wo*32 -> fp16 hi/lo.
// ============================================================================
__global__ __launch_bounds__(256) void combine_f2(
    const float* __restrict__ Wq, const float* __restrict__ Wk,
    const float* __restrict__ Wv, const float* __restrict__ R,
    const float* __restrict__ X, const float* __restrict__ Wo)
{
    const int tid = threadIdx.x;

    // ---- fused convert (X, Wo) ----
    {
        int cid = blockIdx.x + (blockIdx.y << 3) + (blockIdx.z << 6); // 0..191
        int i0 = cid * 256 + tid;
        int st = 192 * 256;
        for (int i = i0; i < MTOK * DD / 4; i += st) {
            float4 v = ((const float4*)X)[i];
            cvt4h(&g_Xf[i * 4], v);
        }
        for (int i = i0; i < DD * DD / 4; i += st) {
            float4 v = ((const float4*)Wo)[i];
            sp4h(&g_Woh[i * 4], &g_Wol[i * 4],
                 make_float4(v.x * 32.0f, v.y * 32.0f, v.z * 32.0f, v.w * 32.0f));
        }
    }

    const int z = blockIdx.z;
    const float* W = (z == 0) ? Wq : ((z == 1) ? Wk : Wv);

    __shared__ __align__(16) __half Wt[32][BKS];            // W rows [k][m] (fp16)
    __shared__ __align__(16) __half Rh[32][BKS], Rl[32][BKS]; // R rows [k][n] split

    const int lane = tid & 31, g = lane >> 2, t = lane & 3;
    const int warp = tid >> 5, wm = warp >> 2, wn = warp & 3;
    const int i0 = blockIdx.y * 128, j0 = blockIdx.x * 128;
    const int kr = tid >> 5, cc = (tid & 31) * 4;

    float acc[4][4][4] = {};
    float4 pa[4], pb[4];
    #pragma unroll
    for (int r = 0; r < 4; r++) {
        pa[r] = *(const float4*)&W[(size_t)(kr + r * 8) * DD + i0 + cc];
        pb[r] = *(const float4*)&R[(size_t)(kr + r * 8) * DD + j0 + cc];
    }

    for (int kt = 0; kt < DD; kt += 32) {
        #pragma unroll
        for (int r = 0; r < 4; r++) {
            cvt4h(&Wt[kr + r * 8][cc], pa[r]);
            sp4h(&Rh[kr + r * 8][cc], &Rl[kr + r * 8][cc], pb[r]);
        }
        __syncthreads();
        if (kt + 32 < DD) {
            #pragma unroll
            for (int r = 0; r < 4; r++) {
                pa[r] = *(const float4*)&W[(size_t)(kt + 32 + kr + r * 8) * DD + i0 + cc];
                pb[r] = *(const float4*)&R[(size_t)(kt + 32 + kr + r * 8) * DD + j0 + cc];
            }
        }
        #pragma unroll
        for (int ks = 0; ks < 2; ks++) {
            const int kk0 = ks * 16;
            uint32_t ah[4][4], bh[2][4], bl[2][4];
            const int arow = kk0 + (lane >> 4) * 8 + (lane & 7);
            const int acol = wm * 64 + ((lane >> 3) & 1) * 8;
            #pragma unroll
            for (int mi = 0; mi < 4; mi++)
                ldsm4t(ah[mi], &Wt[arow][acol + mi * 16]);
            const int brow = kk0 + (lane & 7) + ((lane >> 3) & 1) * 8;
            const int bcol = wn * 32 + (lane >> 4) * 8;
            #pragma unroll
            for (int nj = 0; nj < 2; nj++) {
                ldsm4t(bh[nj], &Rh[brow][bcol + nj * 16]);
                ldsm4t(bl[nj], &Rl[brow][bcol + nj * 16]);
            }
            #pragma unroll
            for (int mi = 0; mi < 4; mi++)
                #pragma unroll
                for (int nj = 0; nj < 2; nj++)
                    #pragma unroll
                    for (int h2 = 0; h2 < 2; h2++) {
                        float* c = acc[mi][nj * 2 + h2];
                        mma16h(c, ah[mi], &bh[nj][h2 * 2]);
                        mma16h(c, ah[mi], &bl[nj][h2 * 2]);
                    }
        }
        __syncthreads();
    }

    __half* Ch = g_Wch[z];
    __half* Cl = g_Wcl[z];
    #pragma unroll
    for (int mi = 0; mi < 4; mi++) {
        int row0 = i0 + wm * 64 + mi * 16 + g;      // k index of Wc
        #pragma unroll
        for (int ni = 0; ni < 4; ni++) {
            int col = j0 + wn * 32 + ni * 8 + 2 * t; // n index of Wc
            sp1h(&Ch[(size_t)row0 * DD + col],     &Cl[(size_t)row0 * DD + col],
                 acc[mi][ni][0] * 32.0f);
            sp1h(&Ch[(size_t)row0 * DD + col + 1], &Cl[(size_t)row0 * DD + col + 1],
                 acc[mi][ni][1] * 32.0f);
            sp1h(&Ch[(size_t)(row0 + 8) * DD + col],     &Cl[(size_t)(row0 + 8) * DD + col],
                 acc[mi][ni][2] * 32.0f);
            sp1h(&Ch[(size_t)(row0 + 8) * DD + col + 1], &Cl[(size_t)(row0 + 8) * DD + col + 1],
                 acc[mi][ni][3] * 32.0f);
        }
    }
}

// ============================================================================
// Kernel 2: P = X @ (32*Wc[z]) (NN), fp16x2, K64 double-buffered cp.async,
// 2 CTAs/SM (R15-proven config). Scatter into fp16 flash layouts.
// buffer: A 128x72 + Bh 64x136 + Bl 64x136 = 26624 halfs = 53.25 KB
// ============================================================================
#define QA_BUF 9216
#define QB_BUF 8704
#define QBUF   (QA_BUF + 2 * QB_BUF)
#define QKV_SMEM (2 * QBUF * 2)

__global__ __launch_bounds__(256, 2) void qkv_f2(const float* __restrict__ ent)
{
    extern __shared__ __half qsm[];
    const int z = blockIdx.z;
    const __half* Wh = g_Wch[z];
    const __half* Wl = g_Wcl[z];

    const int tid = threadIdx.x, lane = tid & 31, g = lane >> 2, t = lane & 3;
    const int warp = tid >> 5, wm = warp >> 2, wn = warp & 3;
    const int m0 = blockIdx.y * 128, j0 = blockIdx.x * 128;
    const int b = m0 >> 11;

    auto fill = [&](int bi, int kt) {
        __half* A  = qsm + bi * QBUF;
        __half* Bh = A + QA_BUF;
        __half* Bl = Bh + QB_BUF;
        #pragma unroll
        for (int i = 0; i < 4; i++) {
            int idx = tid + i * 256;
            int row = idx >> 3, ch = idx & 7;       // A: 128 rows x 64 cols
            cpa16(&A[row * AK64 + ch * 8], &g_Xf[(size_t)(m0 + row) * DD + kt + ch * 8]);
        }
        #pragma unroll
        for (int i = 0; i < 4; i++) {
            int idx = tid + i * 256;
            int row = idx >> 4, ch = idx & 15;      // B: 64 k-rows x 128 cols
            size_t src = (size_t)(kt + row) * DD + j0 + ch * 8;
            cpa16(&Bh[row * BKS + ch * 8], &Wh[src]);
            cpa16(&Bl[row * BKS + ch * 8], &Wl[src]);
        }
    };

    float acc[4][4][4] = {};

    fill(0, 0);  CP_COMMIT();
    fill(1, 64); CP_COMMIT();

    const int NT = DD / 64;   // 16
    for (int it = 0; it < NT; ++it) {
        if (it == NT - 1) { CP_WAIT0(); } else { CP_WAIT1(); }
        __syncthreads();
        const __half* A  = qsm + (it & 1) * QBUF;
        const __half* Bh = A + QA_BUF;
        const __half* Bl = Bh + QB_BUF;
        #pragma unroll
        for (int ks = 0; ks < 4; ks++) {
            const int kk0 = ks * 16;
            uint32_t ah[4][4], bh[2][4], bl[2][4];
            const int arow = wm * 64 + (lane & 15);
            const int ak   = kk0 + (lane >> 4) * 8;
            #pragma unroll
            for (int mi = 0; mi < 4; mi++)
                ldsm4(ah[mi], &A[(arow + mi * 16) * AK64 + ak]);
            const int brow = kk0 + (lane & 7) + ((lane >> 3) & 1) * 8;
            const int bcol = wn * 32 + (lane >> 4) * 8;
            #pragma unroll
            for (int nj = 0; nj < 2; nj++) {
                ldsm4t(bh[nj], &Bh[brow * BKS + bcol + nj * 16]);
                ldsm4t(bl[nj], &Bl[brow * BKS + bcol + nj * 16]);
            }
            #pragma unroll
            for (int mi = 0; mi < 4; mi++)
                #pragma unroll
                for (int nj = 0; nj < 2; nj++)
                    #pragma unroll
                    for (int h2 = 0; h2 < 2; h2++) {
                        float* c = acc[mi][nj * 2 + h2];
                        mma16h(c, ah[mi], &bh[nj][h2 * 2]);
                        mma16h(c, ah[mi], &bl[nj][h2 * 2]);
                    }
        }
        __syncthreads();
        if (it + 2 < NT) { fill(it & 1, (it + 2) * 64); CP_COMMIT(); }
    }

    if (z < 2) {
        __half* OutH = (z == 0) ? g_Qf : g_Kf;
        #pragma unroll
        for (int ni = 0; ni < 4; ni++) {
            int n = j0 + wn * 32 + ni * 8 + 2 * t;    // even
            int h = n >> 6, d = n & 63;
            int pos = (d & 0x30) | ((d & 6) << 1) | ((d & 8) >> 2);
            float s = (z == 0) ? (ent[h] * 0.125f * LOG2E * INV32) : INV32;
            #pragma unroll
            for (int mi = 0; mi < 4; mi++) {
                int m = m0 + wm * 64 + mi * 16 + g;
                int l = m & (LL - 1);
                size_t base = ((size_t)(b * NH + h) * LL + l) * HDIM + pos;
                *(__half2*)&OutH[base] =
                    __floats2half2_rn(acc[mi][ni][0] * s, acc[mi][ni][1] * s);
                *(__half2*)&OutH[base + 8 * HDIM] =
                    __floats2half2_rn(acc[mi][ni][2] * s, acc[mi][ni][3] * s);
            }
        }
    } else {
        #pragma unroll
        for (int ni = 0; ni < 4; ni++) {
            int n = j0 + wn * 32 + ni * 8 + 2 * t;
            int h = n >> 6, d = n & 63;               // d even
            #pragma unroll
            for (int mi = 0; mi < 4; mi++) {
                int m = m0 + wm * 64 + mi * 16 + g;
                int l = m & (LL - 1);
                int l6 = l & 63;
                int pos = (l6 & 0x30) | ((l6 & 6) << 1) | ((l6 & 8) >> 2) | (l6 & 1);
                size_t base = (size_t)(b * NH + h) * LL * HDIM
                            + (size_t)(l >> 6) * 4096 + (size_t)d * 64;
                g_Vt[base + pos]          = __float2half_rn(acc[mi][ni][0] * INV32);
                g_Vt[base + 64 + pos]     = __float2half_rn(acc[mi][ni][1] * INV32);
                g_Vt[base + pos + 2]      = __float2half_rn(acc[mi][ni][2] * INV32);
                g_Vt[base + 64 + pos + 2] = __float2half_rn(acc[mi][ni][3] * INV32);
            }
        }
    }
}

// ============================================================================
// Kernel 3: flash attention v7 — fp16 mma; f16x2 ex2 softmax; l carried as a
// 65th V dim (ones-row mma). Unchanged from R15.
// smem: K 2x64x80 + V 2x72x80 halfs = 43520 B.
// ============================================================================
#define FQS   80
#define KBUF  5120
#define VBUF  5760
#define VBASE 10240
#define FL7_SMEM ((2 * KBUF + 2 * VBUF) * 2)

__global__ __launch_bounds__(256, 1) void flash7()
{
    extern __shared__ __half hsm[];
    const int tid = threadIdx.x, lane = tid & 31, g = lane >> 2, t = lane & 3;
    const int warp = tid >> 5;

    const int bh = blockIdx.y;
    const size_t head = (size_t)bh * LL * HDIM;
    const int q0 = blockIdx.x * 256 + warp * 32;

    uint32_t qa[2][4][4];
    #pragma unroll
    for (int mt = 0; mt < 2; mt++)
        #pragma unroll
        for (int kc = 0; kc < 4; kc++) {
            const __half* qp = &g_Qf[head + (size_t)(q0 + mt * 16 + g) * HDIM + kc * 16 + t * 4];
            uint2 u0 = *(const uint2*)qp;
            uint2 u1 = *(const uint2*)(qp + 8 * HDIM);
            qa[mt][kc][0] = u0.x; qa[mt][kc][1] = u1.x;
            qa[mt][kc][2] = u0.y; qa[mt][kc][3] = u1.y;
        }

    const int frow = tid >> 2;
    const int fch  = (tid & 3) * 2;

    float o[2][8][4] = {};
    float oe[2][4] = {};   // l rides here (ones-row mma output)
    float mv[2][2] = {{-1e30f, -1e30f}, {-1e30f, -1e30f}};

    for (int i = tid; i < 2 * 8 * FQS; i += 256) {
        int bi = i / (8 * FQS), rc = i % (8 * FQS);
        int r = rc / FQS, c = rc % FQS;
        hsm[VBASE + bi * VBUF + (64 + r) * FQS + c] =
            __float2half(r == 0 ? 1.0f : 0.0f);
    }

    {
        const __half* Ks = g_Kf + head;
        const __half* Vs = g_Vt + head;
        #pragma unroll
        for (int i = 0; i < 2; i++) {
            int ch = fch + i;
            cpa16(&hsm[frow * FQS + ch * 8],         &Ks[frow * 64 + ch * 8]);
            cpa16(&hsm[VBASE + frow * FQS + ch * 8], &Vs[frow * 64 + ch * 8]);
        }
    }
    CP_COMMIT();

    for (int it = 0; it < LL / 64; ++it) {
        CP_WAIT0();
        __syncthreads();
        if (it + 1 < LL / 64) {
            const __half* Ks = g_Kf + head + (size_t)(it + 1) * 4096;
            const __half* Vs = g_Vt + head + (size_t)(it + 1) * 4096;
            __half* Kd = hsm + ((it + 1) & 1) * KBUF;
            __half* Vd = hsm + VBASE + ((it + 1) & 1) * VBUF;
            #pragma unroll
            for (int i = 0; i < 2; i++) {
                int ch = fch + i;
                cpa16(&Kd[frow * FQS + ch * 8], &Ks[frow * 64 + ch * 8]);
                cpa16(&Vd[frow * FQS + ch * 8], &Vs[frow * 64 + ch * 8]);
            }
            CP_COMMIT();
        }
        const __half* Ksm = hsm + (it & 1) * KBUF;
        const __half* Vsm = hsm + VBASE + (it & 1) * VBUF;

        float s[2][8][4] = {};
        #pragma unroll
        for (int kc = 0; kc < 4; kc++) {
            #pragma unroll
            for (int nt = 0; nt < 8; nt++) {
                uint2 bv = *(const uint2*)&Ksm[(nt * 8 + g) * FQS + kc * 16 + t * 4];
                uint32_t bf[2] = { bv.x, bv.y };
                mma16h(s[0][nt], qa[0][kc], bf);
                mma16h(s[1][nt], qa[1][kc], bf);
            }
        }

        uint32_t pr[2][8][2];
        #pragma unroll
        for (int mt = 0; mt < 2; mt++) {
            float rmax0 = -1e30f, rmax1 = -1e30f;
            #pragma unroll
            for (int nt = 0; nt < 8; nt++) {
                rmax0 = fmaxf(rmax0, fmaxf(s[mt][nt][0], s[mt][nt][1]));
                rmax1 = fmaxf(rmax1, fmaxf(s[mt][nt][2], s[mt][nt][3]));
            }
            rmax0 = fmaxf(rmax0, __shfl_xor_sync(0xffffffffu, rmax0, 1));
            rmax0 = fmaxf(rmax0, __shfl_xor_sync(0xffffffffu, rmax0, 2));
            rmax1 = fmaxf(rmax1, __shfl_xor_sync(0xffffffffu, rmax1, 1));
            rmax1 = fmaxf(rmax1, __shfl_xor_sync(0xffffffffu, rmax1, 2));

            float nm0 = fmaxf(mv[mt][0], rmax0), nm1 = fmaxf(mv[mt][1], rmax1);
            float c0 = ex2(mv[mt][0] - nm0), c1 = ex2(mv[mt][1] - nm1);
            mv[mt][0] = nm0; mv[mt][1] = nm1;

            #pragma unroll
            for (int nt = 0; nt < 8; nt++) {
                o[mt][nt][0] *= c0; o[mt][nt][1] *= c0;
                o[mt][nt][2] *= c1; o[mt][nt][3] *= c1;
            }
            oe[mt][0] *= c0; oe[mt][1] *= c0;
            oe[mt][2] *= c1; oe[mt][3] *= c1;

            #pragma unroll
            for (int nt = 0; nt < 8; nt++) {
                pr[mt][nt][0] = ex2h2(s[mt][nt][0] - nm0, s[mt][nt][1] - nm0);
                pr[mt][nt][1] = ex2h2(s[mt][nt][2] - nm1, s[mt][nt][3] - nm1);
            }
        }

        #pragma unroll
        for (int kc = 0; kc < 4; kc++) {
            uint32_t pa[2][4];
            #pragma unroll
            for (int mt = 0; mt < 2; mt++) {
                pa[mt][0] = pr[mt][2 * kc][0];
                pa[mt][1] = pr[mt][2 * kc][1];
                pa[mt][2] = pr[mt][2 * kc + 1][0];
                pa[mt][3] = pr[mt][2 * kc + 1][1];
            }
            #pragma unroll
            for (int nt = 0; nt < 8; nt++) {
                uint2 bv = *(const uint2*)&Vsm[(nt * 8 + g) * FQS + kc * 16 + t * 4];
                uint32_t bf[2] = { bv.x, bv.y };
                mma16h(o[0][nt], pa[0], bf);
                mma16h(o[1][nt], pa[1], bf);
            }
            uint2 ev = *(const uint2*)&Vsm[(64 + g) * FQS + kc * 16 + t * 4];
            uint32_t ef[2] = { ev.x, ev.y };
            mma16h(oe[0], pa[0], ef);
            mma16h(oe[1], pa[1], ef);
        }
    }

    const int b = bh >> 4, h = bh & 15;
    #pragma unroll
    for (int mt = 0; mt < 2; mt++) {
        float l0 = __shfl_sync(0xffffffffu, oe[mt][0], lane & 28);
        float l1 = __shfl_sync(0xffffffffu, oe[mt][2], lane & 28);
        float inv0 = 1.0f / l0, inv1 = 1.0f / l1;
        size_t ob0 = ((size_t)b * LL + q0 + mt * 16 + g) * DD + h * HDIM;
        size_t ob1 = ((size_t)b * LL + q0 + mt * 16 + 8 + g) * DD + h * HDIM;
        #pragma unroll
        for (int nt = 0; nt < 8; nt++) {
            int col = nt * 8 + 2 * t;
            *(__half2*)&g_Of[ob0 + col] =
                __floats2half2_rn(o[mt][nt][0] * inv0, o[mt][nt][1] * inv0);
            *(__half2*)&g_Of[ob1 + col] =
                __floats2half2_rn(o[mt][nt][2] * inv1, o[mt][nt][3] * inv1);
        }
    }
}

// ============================================================================
// Kernel 4: Y = O @ (32*Wo)^T / 32 (NT), fp16x2, K64 double-buffered cp.async,
// 2 CTAs/SM (R15-proven config).
// buffer: A 128x72 + Bh 128x72 + Bl 128x72 = 27648 halfs = 55.3 KB
// ============================================================================
#define OBUF (3 * 9216)
#define OUT_SMEM (2 * OBUF * 2)

__global__ __launch_bounds__(256, 2) void out_f2(float* __restrict__ Y)
{
    extern __shared__ __half osm[];
    const int tid = threadIdx.x, lane = tid & 31, g = lane >> 2, t = lane & 3;
    const int warp = tid >> 5, wm = warp >> 2, wn = warp & 3;
    const int m0 = blockIdx.y * 128, j0 = blockIdx.x * 128;

    auto fill = [&](int bi, int kt) {
        __half* A  = osm + bi * OBUF;
        __half* Bh = A + 9216;
        __half* Bl = Bh + 9216;
        #pragma unroll
        for (int i = 0; i < 4; i++) {
            int idx = tid + i * 256;
            int row = idx >> 3, ch = idx & 7;   // 128 rows x 64 cols
            cpa16(&A[row * AK64 + ch * 8], &g_Of[(size_t)(m0 + row) * DD + kt + ch * 8]);
            size_t src = (size_t)(j0 + row) * DD + kt + ch * 8;
            cpa16(&Bh[row * AK64 + ch * 8], &g_Woh[src]);
            cpa16(&Bl[row * AK64 + ch * 8], &g_Wol[src]);
        }
    };

    float acc[4][4][4] = {};

    fill(0, 0);  CP_COMMIT();
    fill(1, 64); CP_COMMIT();

    const int NT = DD / 64;   // 16
    for (int it = 0; it < NT; ++it) {
        if (it == NT - 1) { CP_WAIT0(); } else { CP_WAIT1(); }
        __syncthreads();
        const __half* A  = osm + (it & 1) * OBUF;
        const __half* Bh = A + 9216;
        const __half* Bl = Bh + 9216;
        #pragma unroll
        for (int ks = 0; ks < 4; ks++) {
            const int kk0 = ks * 16;
            uint32_t ah[4][4], bh[2][4], bl[2][4];
            const int arow = wm * 64 + (lane & 15);
            const int ak   = kk0 + (lane >> 4) * 8;
            #pragma unroll
            for (int mi = 0; mi < 4; mi++)
                ldsm4(ah[mi], &A[(arow + mi * 16) * AK64 + ak]);
            const int brow = wn * 32 + (lane & 7) + ((lane >> 4) & 1) * 8;
            const int bk   = kk0 + ((lane >> 3) & 1) * 8;
            #pragma unroll
            for (int nj = 0; nj < 2; nj++) {
                ldsm4(bh[nj], &Bh[(brow + nj * 16) * AK64 + bk]);
                ldsm4(bl[nj], &Bl[(brow + nj * 16) * AK64 + bk]);
            }
            #pragma unroll
            for (int mi = 0; mi < 4; mi++)
                #pragma unroll
                for (int nj = 0; nj < 2; nj++)
                    #pragma unroll
                    for (int h2 = 0; h2 < 2; h2++) {
                        float* c = acc[mi][nj * 2 + h2];
                        mma16h(c, ah[mi], &bh[nj][h2 * 2]);
                        mma16h(c, ah[mi], &bl[nj][h2 * 2]);
                    }
        }
        __syncthreads();
        if (it + 2 < NT) { fill(it & 1, (it + 2) * 64); CP_COMMIT(); }
    }

    #pragma unroll
    for (int mi = 0; mi < 4; mi++) {
        int row0 = m0 + wm * 64 + mi * 16 + g;
        #pragma unroll
        for (int ni = 0; ni < 4; ni++) {
            int col = j0 + wn * 32 + ni * 8 + 2 * t;
            *(float2*)&Y[(size_t)row0 * DD + col] =
                make_float2(acc[mi][ni][0] * INV32, acc[mi][ni][1] * INV32);
            *(float2*)&Y[(size_t)(row0 + 8) * DD + col] =
                make_float2(acc[mi][ni][2] * INV32, acc[mi][ni][3] * INV32);
        }
    }
}

// ============================================================================
// launch
// Inputs: 0=inputs 1=rotation 2=entangle 3=Wq 4=Wk 5=Wv 6=Wo; out (B,L,D) fp32
// ============================================================================
extern "C" void kernel_launch(void* const* d_in, const int* in_sizes, int n_in,
                              void* d_out, int out_size)
{
    const float* X   = (const float*)d_in[0];
    const float* R   = (const float*)d_in[1];
    const float* ent = (const float*)d_in[2];
    const float* Wq  = (const float*)d_in[3];
    const float* Wk  = (const float*)d_in[4];
    const float* Wv  = (const float*)d_in[5];
    const float* Wo  = (const float*)d_in[6];
    float* Y = (float*)d_out;

    cudaFuncSetAttribute(flash7, cudaFuncAttributeMaxDynamicSharedMemorySize, FL7_SMEM);
    cudaFuncSetAttribute(qkv_f2, cudaFuncAttributeMaxDynamicSharedMemorySize, QKV_SMEM);
    cudaFuncSetAttribute(out_f2, cudaFuncAttributeMaxDynamicSharedMemorySize, OUT_SMEM);

    combine_f2<<<dim3(8, 8, 3), 256>>>(Wq, Wk, Wv, R, X, Wo);
    qkv_f2<<<dim3(8, MTOK / 128, 3), 256, QKV_SMEM>>>(ent);
    flash7<<<dim3(LL / 256, BB * NH), 256, FL7_SMEM>>>();
    out_f2<<<dim3(8, MTOK / 128), 256, OUT_SMEM>>>(Y);
}